// round 5
// baseline (speedup 1.0000x reference)
#include <cuda_runtime.h>
#include <cuda_bf16.h>
#include <cstdint>

#define N_TOK 32768
#define DDIM 256
#define KSTAGES 8
#define CDSZ 1024
#define NBLK 512
#define MARGIN 4e-3f

#define KEFF 768
#define NSLICE 12                 // K slices of 64
#define MT 128                    // tokens per CTA
#define NCHUNK 128                // codes per chunk
#define SLICE_B 18432             // 128 rows * 9 granules * 16B
#define GSMEM (4 * SLICE_B)       // A0,A1,B0,B1

typedef unsigned long long u64;

// ------------------------- device scratch (no allocs) -------------------------
__device__ float g_res[N_TOK * DDIM];
__device__ float g_cbT[KSTAGES * DDIM * CDSZ];
__device__ float g_cnorm[KSTAGES * CDSZ];
__device__ float g_rnorm[N_TOK];
__device__ float g_partials[KSTAGES * NBLK];
__device__ __nv_bfloat16 g_asplit[N_TOK * KEFF];            // [hi|hi|lo]
__device__ __nv_bfloat16 g_bsplit[KSTAGES * CDSZ * KEFF];   // [hi|lo|hi]
__device__ int g_enc[N_TOK];
__device__ int g_list[N_TOK];
__device__ int g_acount[KSTAGES];

// ------------------------- helpers -------------------------
__device__ __forceinline__ u64 pack2(float x, float y) {
    u64 r; asm("mov.b64 %0, {%1, %2};" : "=l"(r) : "f"(x), "f"(y)); return r;
}
__device__ __forceinline__ float2 unpack2(u64 v) {
    float2 f; asm("mov.b64 {%0, %1}, %2;" : "=f"(f.x), "=f"(f.y) : "l"(v)); return f;
}
__device__ __forceinline__ u64 fma2(u64 a, u64 b, u64 c) {
    u64 d; asm("fma.rn.f32x2 %0, %1, %2, %3;" : "=l"(d) : "l"(a), "l"(b), "l"(c)); return d;
}
__device__ __forceinline__ uint32_t smem_u32(const void* p) {
    uint32_t a;
    asm("{ .reg .u64 t; cvta.to.shared.u64 t, %1; cvt.u32.u64 %0, t; }" : "=r"(a) : "l"(p));
    return a;
}

#define CP_ASYNC16(s, g) \
    asm volatile("cp.async.cg.shared.global [%0], [%1], 16;" :: "r"(s), "l"(g) : "memory")
#define CP_COMMIT() asm volatile("cp.async.commit_group;" ::: "memory")
#define LDMX4(r, a) \
    asm volatile("ldmatrix.sync.aligned.m8n8.x4.shared.b16 {%0,%1,%2,%3}, [%4];" \
        : "=r"((r)[0]), "=r"((r)[1]), "=r"((r)[2]), "=r"((r)[3]) : "r"(a))
#define MMA16816(d, a, b0, b1) \
    asm volatile("mma.sync.aligned.m16n8k16.row.col.f32.bf16.bf16.f32 " \
        "{%0,%1,%2,%3}, {%4,%5,%6,%7}, {%8,%9}, {%0,%1,%2,%3};" \
        : "+f"((d)[0]), "+f"((d)[1]), "+f"((d)[2]), "+f"((d)[3]) \
        : "r"((a)[0]), "r"((a)[1]), "r"((a)[2]), "r"((a)[3]), "r"(b0), "r"(b1))

// ------------------------- prep kernels -------------------------
__global__ void transpose_cb_kernel(const float* __restrict__ cb) {
    __shared__ float tile[32][33];
    int s = blockIdx.z;
    int d0 = blockIdx.x * 32, c0 = blockIdx.y * 32;
    int tx = threadIdx.x, ty = threadIdx.y;
    const float* src = cb + (size_t)s * CDSZ * DDIM;
    float* dst = g_cbT + (size_t)s * DDIM * CDSZ;
#pragma unroll
    for (int i = 0; i < 32; i += 8)
        tile[ty + i][tx] = src[(size_t)(c0 + ty + i) * DDIM + d0 + tx];
    __syncthreads();
#pragma unroll
    for (int i = 0; i < 32; i += 8)
        dst[(size_t)(d0 + ty + i) * CDSZ + c0 + tx] = tile[tx][ty + i];
}

__global__ void cnorm_kernel(const float* __restrict__ cb) {
    int row = blockIdx.x * 8 + (threadIdx.x >> 5);
    int lane = threadIdx.x & 31;
    const float* p = cb + (size_t)row * DDIM;
    float s = 0.f;
#pragma unroll
    for (int j = 0; j < 8; j++) { float v = p[lane + 32 * j]; s = fmaf(v, v, s); }
#pragma unroll
    for (int off = 16; off; off >>= 1) s += __shfl_xor_sync(0xffffffffu, s, off);
    if (lane == 0) g_cnorm[row] = s;
}

__global__ void prep_b_kernel(const float* __restrict__ cb) {
    int i = blockIdx.x * blockDim.x + threadIdx.x;
    int stride = gridDim.x * blockDim.x;
    for (; i < KSTAGES * CDSZ * DDIM; i += stride) {
        float v = cb[i];
        __nv_bfloat16 h = __float2bfloat16(v);
        __nv_bfloat16 l = __float2bfloat16(v - __bfloat162float(h));
        size_t row = (size_t)(i >> 8);
        int k = i & 255;
        g_bsplit[row * KEFF + k] = h;
        g_bsplit[row * KEFF + 256 + k] = l;
        g_bsplit[row * KEFF + 512 + k] = h;
    }
}

// per-stage: split residual + rnorm + reset ambiguity counter (fused)
__global__ void prep_res_kernel(const float* __restrict__ x, int stage) {
    if (blockIdx.x == 0 && threadIdx.x == 0) g_acount[stage] = 0;
    int wid = threadIdx.x >> 5, lane = threadIdx.x & 31;
    int row = blockIdx.x * 8 + wid;
    const float* src = (stage == 0) ? x : g_res;
    const float* p = src + (size_t)row * DDIM;
    float s = 0.f;
#pragma unroll
    for (int j = 0; j < 8; j++) {
        int idx = lane + 32 * j;
        float v = p[idx];
        __nv_bfloat16 h = __float2bfloat16(v);
        __nv_bfloat16 l = __float2bfloat16(v - __bfloat162float(h));
        g_asplit[(size_t)row * KEFF + idx] = h;
        g_asplit[(size_t)row * KEFF + 256 + idx] = h;
        g_asplit[(size_t)row * KEFF + 512 + idx] = l;
        s = fmaf(v, v, s);
    }
#pragma unroll
    for (int off = 16; off; off >>= 1) s += __shfl_xor_sync(0xffffffffu, s, off);
    if (lane == 0) g_rnorm[row] = s;
}

// ------------------------- HMMA gemm + argmin (approx + gap) -------------------------
__global__ __launch_bounds__(256, 1) void gemm_argmin_kernel(int stage) {
    extern __shared__ char dsm[];
    const uint32_t sA = smem_u32(dsm);             // A0 @0, A1 @SLICE_B
    const uint32_t sB = sA + 2 * SLICE_B;          // B0, B1
    __shared__ float sm_b1[2][MT], sm_b2[2][MT];
    __shared__ int sm_i1[2][MT];

    const int tid = threadIdx.x;
    const int lane = tid & 31, wid = tid >> 5;
    const int warp_m = wid >> 1, warp_n = wid & 1;
    const int tok0 = blockIdx.x * MT;
    const int g = lane >> 2, tig = lane & 3;
    const int tile = lane >> 3, trow = lane & 7;

    const char* Ap = (const char*)(g_asplit + (size_t)tok0 * KEFF);
    const __nv_bfloat16* Ball = g_bsplit + (size_t)stage * CDSZ * KEFF;
    const float* cn = g_cnorm + stage * CDSZ;

    // ldmatrix lane base addresses (stride 9 granules of 16B per row)
    uint32_t aOff[2], bOff[4];
#pragma unroll
    for (int mt = 0; mt < 2; mt++) {
        int r = warp_m * 32 + mt * 16 + (tile & 1) * 8 + trow;
        aOff[mt] = (uint32_t)(r * 9 + (tile >> 1)) * 16;
    }
#pragma unroll
    for (int j = 0; j < 4; j++) {
        int r = warp_n * 64 + j * 16 + (tile >> 1) * 8 + trow;
        bOff[j] = (uint32_t)(r * 9 + (tile & 1)) * 16;
    }

    float R4[4];
#pragma unroll
    for (int t = 0; t < 4; t++) {
        int r = warp_m * 32 + (t >> 1) * 16 + (t & 1) * 8 + g;
        R4[t] = g_rnorm[tok0 + r];
    }

    float tb1[4], tb2[4]; int ti1[4];
#pragma unroll
    for (int t = 0; t < 4; t++) { tb1[t] = 3.4e38f; tb2[t] = 3.4e38f; ti1[t] = 0; }

    for (int ch = 0; ch < CDSZ / NCHUNK; ch++) {
        const char* Bp = (const char*)(Ball + (size_t)ch * NCHUNK * KEFF);
        float acc[2][8][4];
#pragma unroll
        for (int mt = 0; mt < 2; mt++)
#pragma unroll
            for (int nt = 0; nt < 8; nt++)
#pragma unroll
                for (int q = 0; q < 4; q++) acc[mt][nt][q] = 0.f;

        // prime slice 0 into buffer 0
        {
            uint32_t sAb = sA, sBb = sB;
#pragma unroll
            for (int i = 0; i < 4; i++) {
                int idx = i * 256 + tid;
                int r = idx >> 3, c = idx & 7;
                uint32_t so = (uint32_t)(r * 9 + c) * 16;
                CP_ASYNC16(sAb + so, Ap + ((size_t)r * KEFF + c * 8) * 2);
                CP_ASYNC16(sBb + so, Bp + ((size_t)r * KEFF + c * 8) * 2);
            }
            CP_COMMIT();
        }

        for (int s = 0; s < NSLICE; s++) {
            __syncthreads();   // all warps done with buffer (s+1)&1 from slice s-1
            if (s < NSLICE - 1) {
                int sl = s + 1, buf = sl & 1;
                uint32_t sAb = sA + buf * SLICE_B, sBb = sB + buf * SLICE_B;
#pragma unroll
                for (int i = 0; i < 4; i++) {
                    int idx = i * 256 + tid;
                    int r = idx >> 3, c = idx & 7;
                    uint32_t so = (uint32_t)(r * 9 + c) * 16;
                    CP_ASYNC16(sAb + so, Ap + ((size_t)r * KEFF + sl * 64 + c * 8) * 2);
                    CP_ASYNC16(sBb + so, Bp + ((size_t)r * KEFF + sl * 64 + c * 8) * 2);
                }
                CP_COMMIT();
                asm volatile("cp.async.wait_group 1;" ::: "memory");
            } else {
                asm volatile("cp.async.wait_group 0;" ::: "memory");
            }
            __syncthreads();   // slice s data visible to all

            uint32_t bufA = sA + (uint32_t)(s & 1) * SLICE_B;
            uint32_t bufB = sB + (uint32_t)(s & 1) * SLICE_B;
#pragma unroll
            for (int kk = 0; kk < 4; kk++) {
                uint32_t a0[4], a1[4];
                LDMX4(a0, bufA + aOff[0] + kk * 32);
                LDMX4(a1, bufA + aOff[1] + kk * 32);
                uint32_t bf[8][2];
#pragma unroll
                for (int j = 0; j < 4; j++) {
                    uint32_t r[4];
                    LDMX4(r, bufB + bOff[j] + kk * 32);
                    bf[2 * j][0] = r[0]; bf[2 * j][1] = r[1];
                    bf[2 * j + 1][0] = r[2]; bf[2 * j + 1][1] = r[3];
                }
#pragma unroll
                for (int nt = 0; nt < 8; nt++) {
                    MMA16816(acc[0][nt], a0, bf[nt][0], bf[nt][1]);
                    MMA16816(acc[1][nt], a1, bf[nt][0], bf[nt][1]);
                }
            }
        }

        // epilogue: d2 = R - 2*dot + cn, track best/second per token row
#pragma unroll
        for (int nt = 0; nt < 8; nt++) {
            int code = ch * NCHUNK + warp_n * 64 + nt * 8 + 2 * tig;
            float cn0 = __ldg(&cn[code]), cn1 = __ldg(&cn[code + 1]);
#pragma unroll
            for (int mt = 0; mt < 2; mt++) {
                int t0 = mt * 2, t1 = mt * 2 + 1;
                float d;
                d = fmaf(-2.f, acc[mt][nt][0], R4[t0]) + cn0;
                if (d < tb1[t0]) { tb2[t0] = tb1[t0]; tb1[t0] = d; ti1[t0] = code; }
                else if (d < tb2[t0]) tb2[t0] = d;
                d = fmaf(-2.f, acc[mt][nt][1], R4[t0]) + cn1;
                if (d < tb1[t0]) { tb2[t0] = tb1[t0]; tb1[t0] = d; ti1[t0] = code + 1; }
                else if (d < tb2[t0]) tb2[t0] = d;
                d = fmaf(-2.f, acc[mt][nt][2], R4[t1]) + cn0;
                if (d < tb1[t1]) { tb2[t1] = tb1[t1]; tb1[t1] = d; ti1[t1] = code; }
                else if (d < tb2[t1]) tb2[t1] = d;
                d = fmaf(-2.f, acc[mt][nt][3], R4[t1]) + cn1;
                if (d < tb1[t1]) { tb2[t1] = tb1[t1]; tb1[t1] = d; ti1[t1] = code + 1; }
                else if (d < tb2[t1]) tb2[t1] = d;
            }
        }
    }

    // merge across tig lanes (same token rows live in lanes 4g..4g+3)
#pragma unroll
    for (int off = 1; off <= 2; off <<= 1) {
#pragma unroll
        for (int t = 0; t < 4; t++) {
            float ob1 = __shfl_xor_sync(0xffffffffu, tb1[t], off);
            float ob2 = __shfl_xor_sync(0xffffffffu, tb2[t], off);
            int oi = __shfl_xor_sync(0xffffffffu, ti1[t], off);
            float sec;
            if (ob1 < tb1[t] || (ob1 == tb1[t] && oi < ti1[t])) {
                sec = tb1[t]; tb1[t] = ob1; ti1[t] = oi;
            } else sec = ob1;
            tb2[t] = fminf(fminf(tb2[t], ob2), sec);
        }
    }
    if (tig == 0) {
#pragma unroll
        for (int t = 0; t < 4; t++) {
            int r = warp_m * 32 + (t >> 1) * 16 + (t & 1) * 8 + g;
            sm_b1[warp_n][r] = tb1[t];
            sm_b2[warp_n][r] = tb2[t];
            sm_i1[warp_n][r] = ti1[t];
        }
    }
    __syncthreads();
    if (tid < MT) {
        float a1v = sm_b1[0][tid], a2v = sm_b2[0][tid];
        int ai = sm_i1[0][tid];
        float c1v = sm_b1[1][tid], c2v = sm_b2[1][tid];
        int ci = sm_i1[1][tid];
        float m1, m2; int mi;
        if (a1v < c1v || (a1v == c1v && ai < ci)) { m1 = a1v; mi = ai; m2 = fminf(c1v, fminf(a2v, c2v)); }
        else { m1 = c1v; mi = ci; m2 = fminf(a1v, fminf(a2v, c2v)); }
        int token = tok0 + tid;
        g_enc[token] = mi;
        if (__fsub_rn(m2, m1) <= MARGIN) {
            int p = atomicAdd(&g_acount[stage], 1);
            g_list[p] = token;
        }
    }
}

// ------------------------- exact rescue (bit-identical to R2 chain) -------------------------
__global__ __launch_bounds__(256) void fallback_kernel(const float* __restrict__ x, int stage) {
    const float* src = (stage == 0) ? x : g_res;
    const float* cbT = g_cbT + (size_t)stage * DDIM * CDSZ;
    const float* cn = g_cnorm + stage * CDSZ;
    int lane = threadIdx.x & 31;
    int gw = (blockIdx.x * blockDim.x + threadIdx.x) >> 5;
    int nw = (gridDim.x * blockDim.x) >> 5;
    int count = g_acount[stage];

    for (int li = gw; li < count; li += nw) {
        int t = g_list[li];
        const float* r = src + (size_t)t * DDIM;
        float R = g_rnorm[t];
        float bv = 3.4e38f; int bi = 0;
        for (int jb = 0; jb < 4; jb++) {
            u64 acc[4] = {0ull, 0ull, 0ull, 0ull};
            int cbase = lane + 256 * jb;
            for (int k = 0; k < DDIM; k++) {
                float rv = __ldg(&r[k]);
                u64 rp = pack2(rv, rv);
                const float* row = cbT + (size_t)k * CDSZ;
#pragma unroll
                for (int p = 0; p < 4; p++) {
                    int c1 = cbase + 64 * p;
                    acc[p] = fma2(rp, pack2(__ldg(&row[c1]), __ldg(&row[c1 + 32])), acc[p]);
                }
            }
#pragma unroll
            for (int p = 0; p < 4; p++) {
                float2 f = unpack2(acc[p]);
                int c1 = cbase + 64 * p;
                float d2x = __fadd_rn(__fsub_rn(R, __fmul_rn(2.0f, f.x)), __ldg(&cn[c1]));
                float d2y = __fadd_rn(__fsub_rn(R, __fmul_rn(2.0f, f.y)), __ldg(&cn[c1 + 32]));
                if (d2x < bv) { bv = d2x; bi = c1; }
                if (d2y < bv) { bv = d2y; bi = c1 + 32; }
            }
        }
#pragma unroll
        for (int off = 16; off; off >>= 1) {
            float ov = __shfl_xor_sync(0xffffffffu, bv, off);
            int oi = __shfl_xor_sync(0xffffffffu, bi, off);
            if (ov < bv || (ov == bv && oi < bi)) { bv = ov; bi = oi; }
        }
        if (lane == 0) g_enc[t] = bi;
    }
}

// ------------------------- residual update + loss + enc out (proven R2 chain) ------------
__global__ __launch_bounds__(128) void update_kernel(const float* __restrict__ x,
                                                     const float* __restrict__ cb,
                                                     int stage, float* __restrict__ encf) {
    __shared__ float wsum[4];
    const float* src = (stage == 0) ? x : g_res;
    const int tid = threadIdx.x;
    const int warpId = tid >> 5, lane = tid & 31;
    const int tok0 = blockIdx.x * 64;
    float lsum = 0.f;
    for (int t = warpId; t < 64; t += 4) {
        int token = tok0 + t;
        int e = g_enc[token];
        const float* crow = cb + (size_t)e * DDIM;
#pragma unroll
        for (int jj = 0; jj < 8; jj++) {
            int d = lane + jj * 32;
            float r = __ldg(&src[(size_t)token * DDIM + d]);
            float c = __ldg(&crow[d]);
            float nr = r - c;
            g_res[(size_t)token * DDIM + d] = nr;
            lsum = fmaf(nr, nr, lsum);
        }
        if (lane == 0) encf[(size_t)token * KSTAGES + stage] = (float)e;
    }
#pragma unroll
    for (int off = 16; off; off >>= 1) lsum += __shfl_xor_sync(0xffffffffu, lsum, off);
    if (lane == 0) wsum[warpId] = lsum;
    __syncthreads();
    if (tid == 0)
        g_partials[stage * NBLK + blockIdx.x] = wsum[0] + wsum[1] + wsum[2] + wsum[3];
}

// ------------------------- epilogue -------------------------
__global__ void finalize_kernel(float* __restrict__ out) {
    __shared__ float sh[256];
    int tid = threadIdx.x;
    float s = 0.f;
    for (int i = tid; i < KSTAGES * NBLK; i += 256) s += g_partials[i];
    sh[tid] = s;
    __syncthreads();
    for (int off = 128; off; off >>= 1) {
        if (tid < off) sh[tid] += sh[tid + off];
        __syncthreads();
    }
    if (tid == 0) {
        float loss = sh[0] * (1.0f / (float)((size_t)N_TOK * DDIM));
        out[0] = loss;
        out[1] = loss;
    }
}

__global__ void quant_kernel(const float* __restrict__ x, float* __restrict__ out) {
    float* q = out + 2 + (size_t)N_TOK * KSTAGES;
    int i = blockIdx.x * blockDim.x + threadIdx.x;
    int stride = gridDim.x * blockDim.x;
    for (; i < N_TOK * DDIM; i += stride) q[i] = x[i] - g_res[i];
}

// ------------------------- launch -------------------------
extern "C" void kernel_launch(void* const* d_in, const int* in_sizes, int n_in,
                              void* d_out, int out_size) {
    const float* x  = (const float*)d_in[0];
    const float* cb = (const float*)d_in[1];
    if (n_in >= 2 && in_sizes[0] == KSTAGES * CDSZ * DDIM && in_sizes[1] == N_TOK * DDIM) {
        const float* t = x; x = cb; cb = t;
    }
    float* out = (float*)d_out;

    cudaFuncSetAttribute(gemm_argmin_kernel,
                         cudaFuncAttributeMaxDynamicSharedMemorySize, GSMEM);

    transpose_cb_kernel<<<dim3(8, 32, 8), dim3(32, 8)>>>(cb);
    cnorm_kernel<<<(KSTAGES * CDSZ) / 8, 256>>>(cb);
    prep_b_kernel<<<2048, 256>>>(cb);

    for (int s = 0; s < KSTAGES; s++) {
        prep_res_kernel<<<N_TOK / 8, 256>>>(x, s);
        gemm_argmin_kernel<<<N_TOK / MT, 256, GSMEM>>>(s);
        fallback_kernel<<<128, 256>>>(x, s);
        update_kernel<<<NBLK, 128>>>(x, cb + (size_t)s * CDSZ * DDIM, s, out + 2);
    }

    finalize_kernel<<<1, 256>>>(out);
    quant_kernel<<<4096, 256>>>(x, out);
}

// round 6
// speedup vs baseline: 5.1621x; 5.1621x over previous
#include <cuda_runtime.h>
#include <cstdint>

#define N_TOK 32768
#define DDIM 256
#define KSTAGES 8
#define CDSZ 1024

#define TM 64
#define TN 256
#define TKC 32
#define AS_STRIDE 264
#define NBLK (N_TOK / TM)                 // 512
// Bs: [32 k][4 q][16 tx] float4, q-rotated
#define BS_F4 (TKC * 4 * 16)
#define SMEM_BYTES (TM * AS_STRIDE * 4 + BS_F4 * 16)   // 67584 + 32768 = 100352

typedef unsigned long long u64;

// ------------------------- device scratch (no allocs) -------------------------
__device__ float g_res[N_TOK * DDIM];               // running residual (32 MB)
__device__ float g_cbT[KSTAGES * DDIM * CDSZ];      // d-major codebooks (8 MB)
__device__ float g_cnorm[KSTAGES * CDSZ];           // ||c||^2
__device__ float g_partials[KSTAGES * NBLK];        // per-block loss partials

__device__ __forceinline__ u64 pack2(float x, float y) {
    u64 r; asm("mov.b64 %0, {%1, %2};" : "=l"(r) : "f"(x), "f"(y)); return r;
}
__device__ __forceinline__ float2 unpack2(u64 v) {
    float2 f; asm("mov.b64 {%0, %1}, %2;" : "=f"(f.x), "=f"(f.y) : "l"(v)); return f;
}
__device__ __forceinline__ u64 fma2(u64 a, u64 b, u64 c) {
    u64 d; asm("fma.rn.f32x2 %0, %1, %2, %3;" : "=l"(d) : "l"(a), "l"(b), "l"(c)); return d;
}

// ------------------------- prep: transpose + code norms -------------------------
__global__ void transpose_cb_kernel(const float* __restrict__ cb) {
    __shared__ float tile[32][33];
    int s = blockIdx.z;
    int d0 = blockIdx.x * 32, c0 = blockIdx.y * 32;
    int tx = threadIdx.x, ty = threadIdx.y;
    const float* src = cb + (size_t)s * CDSZ * DDIM;
    float* dst = g_cbT + (size_t)s * DDIM * CDSZ;
#pragma unroll
    for (int i = 0; i < 32; i += 8)
        tile[ty + i][tx] = src[(size_t)(c0 + ty + i) * DDIM + d0 + tx];
    __syncthreads();
#pragma unroll
    for (int i = 0; i < 32; i += 8)
        dst[(size_t)(d0 + ty + i) * CDSZ + c0 + tx] = tile[tx][ty + i];
}

__global__ void cnorm_kernel(const float* __restrict__ cb) {
    int row = blockIdx.x * 8 + (threadIdx.x >> 5);   // 0 .. 8191
    int lane = threadIdx.x & 31;
    const float* p = cb + (size_t)row * DDIM;
    float s = 0.f;
#pragma unroll
    for (int j = 0; j < 8; j++) { float v = p[lane + 32 * j]; s = fmaf(v, v, s); }
#pragma unroll
    for (int off = 16; off; off >>= 1) s += __shfl_xor_sync(0xffffffffu, s, off);
    if (lane == 0) g_cnorm[row] = s;
}

// ------------------------- per-stage fused GEMM+argmin+update -------------------------
extern __shared__ float smem_dyn[];

__global__ __launch_bounds__(128, 2) void rvq_stage_kernel(
    const float* __restrict__ x,     // residual source for stage 0
    const float* __restrict__ cb,    // this stage's codebook [CDSZ*DDIM], c-major
    int stage,
    float* __restrict__ encf)        // d_out + 2 (enc region, token-major)
{
    float* As = smem_dyn;                                   // [TM][AS_STRIDE]
    float4* Bs4 = (float4*)(smem_dyn + TM * AS_STRIDE);     // [32][4][16] float4 (q-rotated)
    __shared__ float rnorm_s[TM];
    __shared__ int bestI_s[TM];
    __shared__ float wsum[4];

    const int tid = threadIdx.x;
    const int tx = tid & 15, ty = tid >> 4;                 // tx 0..15 (codes), ty 0..7 (tokens)
    const int tok0 = blockIdx.x * TM;
    const float* cbT = g_cbT + (size_t)stage * DDIM * CDSZ;
    const float* cnorm = g_cnorm + stage * CDSZ;
    const float* src = (stage == 0) ? x : g_res;

    // load 64x256 residual tile (float4, coalesced)
#pragma unroll
    for (int it = 0; it < 32; it++) {
        int idx4 = it * 128 + tid;
        int r = idx4 >> 6;
        int c4 = (idx4 & 63) << 2;
        float4 v = *(const float4*)&src[(size_t)(tok0 + r) * DDIM + c4];
        *(float4*)&As[r * AS_STRIDE + c4] = v;
    }
    __syncthreads();

    // rnorm per token (XLA-order: lane-strided fma + xor butterfly) — identical to R2
    {
        const int warpId = tid >> 5, lane = tid & 31;
        for (int t = warpId; t < TM; t += 4) {
            float s = 0.f;
#pragma unroll
            for (int j = 0; j < 8; j++) {
                float v = As[t * AS_STRIDE + lane + 32 * j];
                s = fmaf(v, v, s);
            }
#pragma unroll
            for (int off = 16; off; off >>= 1) s += __shfl_xor_sync(0xffffffffu, s, off);
            if (lane == 0) rnorm_s[t] = s;
        }
    }

    float bestVr[8];
    int bestIr[8];
#pragma unroll
    for (int i = 0; i < 8; i++) { bestVr[i] = 3.4e38f; bestIr[i] = 0; }

    for (int ct = 0; ct < CDSZ; ct += TN) {
        // pure dot accumulators: 8 tokens x 16 codes (8 u64 each), k ascending 0..255
        u64 acc[8][8];
#pragma unroll
        for (int i = 0; i < 8; i++)
#pragma unroll
            for (int j = 0; j < 8; j++) acc[i][j] = 0ull;

        for (int kk = 0; kk < DDIM; kk += TKC) {
            __syncthreads();   // protect Bs from previous iteration's readers
            // load B slice: 32 k x 256 codes, q-major with XOR rotation
#pragma unroll
            for (int it = 0; it < 16; it++) {
                int g = it * 128 + tid;          // 0..2047 float4 granules
                int k = g >> 6;                  // 0..31
                int rem = g & 63;                // codes 4*rem .. 4*rem+3
                int txg = rem >> 2, q = rem & 3;
                float4 v = *(const float4*)&cbT[(size_t)(kk + k) * CDSZ + ct + rem * 4];
                Bs4[(k * 4 + q) * 16 + ((txg + 4 * q) & 15)] = v;
            }
            __syncthreads();   // publish Bs (and As on first pass)

#pragma unroll
            for (int k4 = 0; k4 < TKC; k4 += 4) {
                float4 a4[8];
#pragma unroll
                for (int i = 0; i < 8; i++)
                    a4[i] = *(const float4*)&As[(ty * 8 + i) * AS_STRIDE + kk + k4];
#pragma unroll
                for (int dk = 0; dk < 4; dk++) {
                    const ulonglong2* bp = (const ulonglong2*)(Bs4 + (k4 + dk) * 64);
                    ulonglong2 B0 = bp[tx];
                    ulonglong2 B1 = bp[16 + ((tx + 4) & 15)];
                    ulonglong2 B2 = bp[32 + ((tx + 8) & 15)];
                    ulonglong2 B3 = bp[48 + ((tx + 12) & 15)];
#pragma unroll
                    for (int i = 0; i < 8; i++) {
                        float av = ((const float*)&a4[i])[dk];
                        u64 ap = pack2(av, av);
                        acc[i][0] = fma2(ap, B0.x, acc[i][0]);
                        acc[i][1] = fma2(ap, B0.y, acc[i][1]);
                        acc[i][2] = fma2(ap, B1.x, acc[i][2]);
                        acc[i][3] = fma2(ap, B1.y, acc[i][3]);
                        acc[i][4] = fma2(ap, B2.x, acc[i][4]);
                        acc[i][5] = fma2(ap, B2.y, acc[i][5]);
                        acc[i][6] = fma2(ap, B3.x, acc[i][6]);
                        acc[i][7] = fma2(ap, B3.y, acc[i][7]);
                    }
                }
            }
        }

        // d2 = (rnorm - 2*dot) + cnorm, explicit op order; strict-< lowest-index argmin
        float2 cnp[8];
#pragma unroll
        for (int j = 0; j < 8; j++)
            cnp[j] = *(const float2*)&cnorm[ct + tx * 16 + j * 2];

#pragma unroll
        for (int i = 0; i < 8; i++) {
            float R = rnorm_s[ty * 8 + i];
            float bv = 3.4e38f; int bi = 0;
#pragma unroll
            for (int j = 0; j < 8; j++) {
                float2 f = unpack2(acc[i][j]);
                int c0 = ct + tx * 16 + j * 2;
                float d2x = __fadd_rn(__fsub_rn(R, __fmul_rn(2.0f, f.x)), cnp[j].x);
                float d2y = __fadd_rn(__fsub_rn(R, __fmul_rn(2.0f, f.y)), cnp[j].y);
                if (d2x < bv) { bv = d2x; bi = c0; }
                if (d2y < bv) { bv = d2y; bi = c0 + 1; }
            }
#pragma unroll
            for (int off = 8; off; off >>= 1) {
                float ov = __shfl_xor_sync(0xffffffffu, bv, off);
                int oi = __shfl_xor_sync(0xffffffffu, bi, off);
                if (ov < bv || (ov == bv && oi < bi)) { bv = ov; bi = oi; }
            }
            if (bv < bestVr[i]) { bestVr[i] = bv; bestIr[i] = bi; }
        }
    }
    if (tx == 0) {
#pragma unroll
        for (int i = 0; i < 8; i++) bestI_s[ty * 8 + i] = bestIr[i];
    }
    __syncthreads();

    // residual update + deterministic loss partial + enc output (identical to R2)
    const int warpId = tid >> 5, lane = tid & 31;
    float lsum = 0.f;
    for (int t = warpId; t < TM; t += 4) {
        int e = bestI_s[t];
        const float* crow = cb + (size_t)e * DDIM;
#pragma unroll
        for (int jj = 0; jj < 8; jj++) {
            int d = lane + jj * 32;
            float r = As[t * AS_STRIDE + d];
            float c = __ldg(&crow[d]);
            float nr = r - c;
            g_res[(size_t)(tok0 + t) * DDIM + d] = nr;
            lsum = fmaf(nr, nr, lsum);
        }
        if (lane == 0) encf[(size_t)(tok0 + t) * KSTAGES + stage] = (float)e;
    }
#pragma unroll
    for (int off = 16; off; off >>= 1) lsum += __shfl_xor_sync(0xffffffffu, lsum, off);
    if (lane == 0) wsum[warpId] = lsum;
    __syncthreads();
    if (tid == 0)
        g_partials[stage * NBLK + blockIdx.x] = wsum[0] + wsum[1] + wsum[2] + wsum[3];
}

// ------------------------- epilogue -------------------------
__global__ void finalize_kernel(float* __restrict__ out) {
    __shared__ float sh[256];
    int tid = threadIdx.x;
    float s = 0.f;
    for (int i = tid; i < KSTAGES * NBLK; i += 256) s += g_partials[i];
    sh[tid] = s;
    __syncthreads();
    for (int off = 128; off; off >>= 1) {
        if (tid < off) sh[tid] += sh[tid + off];
        __syncthreads();
    }
    if (tid == 0) {
        float loss = sh[0] * (1.0f / (float)((size_t)N_TOK * DDIM));
        out[0] = loss;   // loss_cd
        out[1] = loss;   // loss_enc (forward values identical)
    }
}

__global__ void quant_kernel(const float* __restrict__ x, float* __restrict__ out) {
    float* q = out + 2 + (size_t)N_TOK * KSTAGES;
    int i = blockIdx.x * blockDim.x + threadIdx.x;
    int stride = gridDim.x * blockDim.x;
    for (; i < N_TOK * DDIM; i += stride) q[i] = x[i] - g_res[i];
}

// ------------------------- launch -------------------------
extern "C" void kernel_launch(void* const* d_in, const int* in_sizes, int n_in,
                              void* d_out, int out_size) {
    const float* x  = (const float*)d_in[0];
    const float* cb = (const float*)d_in[1];
    if (n_in >= 2 && in_sizes[0] == KSTAGES * CDSZ * DDIM && in_sizes[1] == N_TOK * DDIM) {
        const float* t = x; x = cb; cb = t;
    }
    float* out = (float*)d_out;

    cudaFuncSetAttribute(rvq_stage_kernel,
                         cudaFuncAttributeMaxDynamicSharedMemorySize, SMEM_BYTES);

    transpose_cb_kernel<<<dim3(8, 32, 8), dim3(32, 8)>>>(cb);
    cnorm_kernel<<<(KSTAGES * CDSZ) / 8, 256>>>(cb);

    for (int s = 0; s < KSTAGES; s++) {
        rvq_stage_kernel<<<NBLK, 128, SMEM_BYTES>>>(
            x, cb + (size_t)s * CDSZ * DDIM, s, out + 2);
    }

    finalize_kernel<<<1, 256>>>(out);
    quant_kernel<<<4096, 256>>>(x, out);
}